// round 5
// baseline (speedup 1.0000x reference)
#include <cuda_runtime.h>
#include <cuda_fp16.h>
#include <cstdint>

#define NB   4
#define NSEQ 4096
#define CDIM 512
#define DDIM 64

// fp16 scratch (allocation-free rule: __device__ globals)
__device__ __half g_qh[NB * NSEQ * DDIM];   // Q = x @ g
__device__ __half g_kh[NB * NSEQ * DDIM];   // K = input_h @ f
__device__ __half g_hh[NB * NSEQ * CDIM];   // input_h fp16

#define SWZ(x) ((x) ^ (((x) >> 3) & 0x70))

// ---------------------------------------------------------------------------
__device__ __forceinline__ uint32_t smem_u32(const void* p) {
    uint32_t a;
    asm("{ .reg .u64 t; cvta.to.shared.u64 t, %1; cvt.u32.u64 %0, t; }" : "=r"(a) : "l"(p));
    return a;
}
__device__ __forceinline__ void cp16(uint32_t s, const void* g) {
    asm volatile("cp.async.cg.shared.global [%0], [%1], 16;" :: "r"(s), "l"(g));
}
#define CP_COMMIT() asm volatile("cp.async.commit_group;" ::: "memory")
#define CP_WAIT1()  asm volatile("cp.async.wait_group 1;" ::: "memory")

__device__ __forceinline__ void ldsm4(uint32_t* r, uint32_t a) {
    asm volatile("ldmatrix.sync.aligned.m8n8.x4.shared.b16 {%0,%1,%2,%3}, [%4];"
        : "=r"(r[0]), "=r"(r[1]), "=r"(r[2]), "=r"(r[3]) : "r"(a));
}
__device__ __forceinline__ void ldsm4t(uint32_t* r, uint32_t a) {
    asm volatile("ldmatrix.sync.aligned.m8n8.x4.trans.shared.b16 {%0,%1,%2,%3}, [%4];"
        : "=r"(r[0]), "=r"(r[1]), "=r"(r[2]), "=r"(r[3]) : "r"(a));
}
__device__ __forceinline__ void mma16816(float* d, const uint32_t* a,
                                         uint32_t b0, uint32_t b1) {
    asm volatile(
        "mma.sync.aligned.m16n8k16.row.col.f32.f16.f16.f32 "
        "{%0,%1,%2,%3}, {%4,%5,%6,%7}, {%8,%9}, {%0,%1,%2,%3};"
        : "+f"(d[0]), "+f"(d[1]), "+f"(d[2]), "+f"(d[3])
        : "r"(a[0]), "r"(a[1]), "r"(a[2]), "r"(a[3]), "r"(b0), "r"(b1));
}
__device__ __forceinline__ void sts32(uint32_t a, uint32_t v) {
    asm volatile("st.shared.b32 [%0], %1;" :: "r"(a), "r"(v) : "memory");
}
__device__ __forceinline__ void sts128(uint32_t a, uint32_t v0, uint32_t v1,
                                       uint32_t v2, uint32_t v3) {
    asm volatile("st.shared.v4.b32 [%0], {%1,%2,%3,%4};"
        :: "r"(a), "r"(v0), "r"(v1), "r"(v2), "r"(v3) : "memory");
}

// ---------------------------------------------------------------------------
// Projection via HMMA: O[16384,64] = fp16(A[16384,512]) @ fp16(W[512,64]).
// doF side-effect: writes converted in_h tile to g_hh.
// ---------------------------------------------------------------------------
__global__ __launch_bounds__(256) void proj_kernel(
    const float* __restrict__ x, const float* __restrict__ in_h,
    const float* __restrict__ f, const float* __restrict__ g)
{
    const bool doF = (blockIdx.z == 1);
    const float* A  = doF ? in_h : x;
    const float* Wm = doF ? f : g;
    __half* O       = doF ? g_kh : g_qh;

    __shared__ char psm[16384 + 8192];
    const uint32_t sa = smem_u32(psm);
    const uint32_t sw = sa + 16384;

    const int m0  = blockIdx.x * 128;
    const int tid = threadIdx.x;
    const int wid = tid >> 5, lane = tid & 31;
    const int l16 = lane & 15, lhi = lane & 16;
    const int w16 = wid * 16;

    float acc[8][4];
    #pragma unroll
    for (int i = 0; i < 8; i++)
        #pragma unroll
        for (int j = 0; j < 4; j++) acc[i][j] = 0.f;

    for (int k0 = 0; k0 < CDIM; k0 += 64) {
        #pragma unroll
        for (int i = 0; i < 4; i++) {
            int lin = tid + i * 256;
            int row = lin >> 3, c8 = lin & 7;
            const float4* ap = (const float4*)(A + (size_t)(m0 + row) * CDIM + k0 + c8 * 8);
            float4 v0 = ap[0], v1 = ap[1];
            __half2 h0 = __floats2half2_rn(v0.x, v0.y);
            __half2 h1 = __floats2half2_rn(v0.z, v0.w);
            __half2 h2 = __floats2half2_rn(v1.x, v1.y);
            __half2 h3 = __floats2half2_rn(v1.z, v1.w);
            sts128(sa + SWZ(row * 128 + c8 * 16),
                   *(uint32_t*)&h0, *(uint32_t*)&h1, *(uint32_t*)&h2, *(uint32_t*)&h3);
            if (doF) {
                uint4 pk = make_uint4(*(uint32_t*)&h0, *(uint32_t*)&h1,
                                      *(uint32_t*)&h2, *(uint32_t*)&h3);
                *(uint4*)(g_hh + (size_t)(m0 + row) * CDIM + k0 + c8 * 8) = pk;
            }
        }
        #pragma unroll
        for (int i = 0; i < 2; i++) {
            int lin = tid + i * 256;
            int kk = lin >> 3, n8 = lin & 7;
            const float4* wp = (const float4*)(Wm + (size_t)(k0 + kk) * DDIM + n8 * 8);
            float4 v0 = wp[0], v1 = wp[1];
            __half2 h0 = __floats2half2_rn(v0.x, v0.y);
            __half2 h1 = __floats2half2_rn(v0.z, v0.w);
            __half2 h2 = __floats2half2_rn(v1.x, v1.y);
            __half2 h3 = __floats2half2_rn(v1.z, v1.w);
            sts128(sw + SWZ(kk * 128 + n8 * 16),
                   *(uint32_t*)&h0, *(uint32_t*)&h1, *(uint32_t*)&h2, *(uint32_t*)&h3);
        }
        __syncthreads();

        #pragma unroll
        for (int ks = 0; ks < 4; ks++) {
            uint32_t a[4];
            ldsm4(a, sa + SWZ((w16 + l16) * 128 + ks * 32 + lhi));
            #pragma unroll
            for (int cb = 0; cb < 4; cb++) {
                uint32_t b[4];
                ldsm4t(b, sw + SWZ((ks * 16 + l16) * 128 + cb * 32 + lhi));
                mma16816(acc[2 * cb],     a, b[0], b[1]);
                mma16816(acc[2 * cb + 1], a, b[2], b[3]);
            }
        }
        __syncthreads();
    }

    const int r = w16 + (lane >> 2);
    const int cb2 = (lane & 3) * 2;
    #pragma unroll
    for (int nt = 0; nt < 8; nt++) {
        __half2 v0 = __floats2half2_rn(acc[nt][0], acc[nt][1]);
        __half2 v1 = __floats2half2_rn(acc[nt][2], acc[nt][3]);
        *(__half2*)(O + (size_t)(m0 + r) * DDIM + nt * 8 + cb2)     = v0;
        *(__half2*)(O + (size_t)(m0 + r + 8) * DDIM + nt * 8 + cb2) = v1;
    }
}

// ---------------------------------------------------------------------------
// Fused attention via HMMA. 256 thr / 8 warps; tile 64q x 256c; KT=64;
// 2-stage cp.async pipeline; SMEM 99584 B -> 2 CTAs/SM.
// ---------------------------------------------------------------------------
#define SM_Q     0        // [64][64] f16 SW128 (8 KB)
#define SM_K     8192     // 2 x [64][64] f16 (2 x 8 KB)
#define SM_P     24576    // [64q][64k] f16 (8 KB)
#define SM_H     32768    // 2 x (4 panels [64k][64c]) (2 x 32 KB)
#define SM_DSUM  98304    // 64*4 f32
#define SM_DINV  99328    // 64 f32
#define SMEM_TOTAL 99584

__global__ __launch_bounds__(256, 2)
void attn_kernel(const float* __restrict__ x, const float* __restrict__ gamma,
                 float* __restrict__ out)
{
    extern __shared__ char smem[];
    const uint32_t sb = smem_u32(smem);
    const int tid = threadIdx.x;
    const int wid = tid >> 5, lane = tid & 31;
    const int l16 = lane & 15;
    const int lhi = lane & 16;
    const int qw  = wid >> 2;            // 0..1 (32-q group)
    const int kw  = wid & 3;             // 0..3 (16-k group / 64-c panel)
    const int q0  = qw * 32;
    const int kS0 = kw * 16;

    const int qt = blockIdx.x, half = blockIdx.y, b = blockIdx.z;
    const int qbase = qt * 64, chbase = half * 256;
    const size_t boff = (size_t)b * NSEQ;

    float acc[2][8][4];
    #pragma unroll
    for (int i = 0; i < 2; i++)
        #pragma unroll
        for (int j = 0; j < 8; j++)
            #pragma unroll
            for (int k = 0; k < 4; k++) acc[i][j][k] = 0.f;
    float dpv[4] = {0.f, 0.f, 0.f, 0.f};

    // staging coords
    const int srow = tid >> 3, sc8 = tid & 7;   // K/Q rows (0..31), +32
    const int hk = tid >> 5, hc16 = tid & 31;   // H rows (0..7), step 8

    // ---- Prologue: Q + tile 0 ----
    #pragma unroll
    for (int i = 0; i < 2; i++) {
        int row = srow + i * 32;
        cp16(sb + SM_Q + SWZ(row * 128 + sc8 * 16),
             g_qh + (boff + qbase + row) * DDIM + sc8 * 8);
        cp16(sb + SM_K + SWZ(row * 128 + sc8 * 16),
             g_kh + (boff + row) * DDIM + sc8 * 8);
    }
    #pragma unroll
    for (int i = 0; i < 8; i++) {
        int k = hk + i * 8;
        cp16(sb + SM_H + (hc16 >> 3) * 8192 + SWZ(k * 128 + (hc16 & 7) * 16),
             g_hh + (boff + k) * CDIM + chbase + hc16 * 8);
    }
    CP_COMMIT();

    for (int t = 0; t < 64; t++) {
        __syncthreads();  // everyone done reading buf[(t+1)&1] from iter t-1

        if (t < 63) {
            const int kt1 = (t + 1) * 64;
            const uint32_t kbuf = sb + SM_K + ((t + 1) & 1) * 8192;
            const uint32_t hbuf = sb + SM_H + ((t + 1) & 1) * 32768;
            #pragma unroll
            for (int i = 0; i < 2; i++) {
                int row = srow + i * 32;
                cp16(kbuf + SWZ(row * 128 + sc8 * 16),
                     g_kh + (boff + kt1 + row) * DDIM + sc8 * 8);
            }
            #pragma unroll
            for (int i = 0; i < 8; i++) {
                int k = hk + i * 8;
                cp16(hbuf + (hc16 >> 3) * 8192 + SWZ(k * 128 + (hc16 & 7) * 16),
                     g_hh + (boff + kt1 + k) * CDIM + chbase + hc16 * 8);
            }
        }
        CP_COMMIT();
        CP_WAIT1();
        __syncthreads();

        const uint32_t kbase = sb + SM_K + (t & 1) * 8192;

        // ---- S = Q @ K^T (warp: 32q x 16k) ----
        float sacc[2][2][4];
        #pragma unroll
        for (int i = 0; i < 2; i++)
            #pragma unroll
            for (int j = 0; j < 2; j++)
                #pragma unroll
                for (int k = 0; k < 4; k++) sacc[i][j][k] = 0.f;

        #pragma unroll
        for (int ks = 0; ks < 4; ks++) {
            uint32_t a0[4], a1[4], bb[4];
            ldsm4(a0, sb + SM_Q + SWZ((q0 + l16) * 128 + ks * 32 + lhi));
            ldsm4(a1, sb + SM_Q + SWZ((q0 + 16 + l16) * 128 + ks * 32 + lhi));
            ldsm4(bb, kbase + SWZ((kS0 + l16) * 128 + ks * 32 + lhi));
            mma16816(sacc[0][0], a0, bb[0], bb[2]);
            mma16816(sacc[0][1], a0, bb[1], bb[3]);
            mma16816(sacc[1][0], a1, bb[0], bb[2]);
            mma16816(sacc[1][1], a1, bb[1], bb[3]);
        }

        // ---- P = exp(S) -> SMEM fp16 ----
        #pragma unroll
        for (int mt = 0; mt < 2; mt++) {
            #pragma unroll
            for (int nt = 0; nt < 2; nt++) {
                float p0 = __expf(sacc[mt][nt][0]);
                float p1 = __expf(sacc[mt][nt][1]);
                float p2 = __expf(sacc[mt][nt][2]);
                float p3 = __expf(sacc[mt][nt][3]);
                dpv[mt * 2 + 0] += p0 + p1;
                dpv[mt * 2 + 1] += p2 + p3;
                int colb = (kS0 + nt * 8 + (lane & 3) * 2) * 2;
                int ra = q0 + mt * 16 + (lane >> 2);
                __half2 ha = __floats2half2_rn(p0, p1);
                __half2 hb = __floats2half2_rn(p2, p3);
                sts32(sb + SM_P + SWZ(ra * 128 + colb), *(uint32_t*)&ha);
                sts32(sb + SM_P + SWZ((ra + 8) * 128 + colb), *(uint32_t*)&hb);
            }
        }
        __syncthreads();

        // ---- O += P @ H (warp: 32q x 64c, panel kw) ----
        const uint32_t hpan = sb + SM_H + (t & 1) * 32768 + kw * 8192;
        #pragma unroll
        for (int ks = 0; ks < 4; ks++) {
            const int kk = ks * 16;
            uint32_t a0[4], a1[4];
            ldsm4(a0, sb + SM_P + SWZ((q0 + l16) * 128 + kk * 2 + lhi));
            ldsm4(a1, sb + SM_P + SWZ((q0 + 16 + l16) * 128 + kk * 2 + lhi));
            #pragma unroll
            for (int cb = 0; cb < 4; cb++) {
                uint32_t r[4];
                ldsm4t(r, hpan + SWZ((kk + l16) * 128 + cb * 32 + lhi));
                mma16816(acc[0][2 * cb],     a0, r[0], r[1]);
                mma16816(acc[0][2 * cb + 1], a0, r[2], r[3]);
                mma16816(acc[1][2 * cb],     a1, r[0], r[1]);
                mma16816(acc[1][2 * cb + 1], a1, r[2], r[3]);
            }
        }
    }

    // ---- denominators ----
    float* dsum = (float*)(smem + SM_DSUM);
    float* dinv = (float*)(smem + SM_DINV);
    #pragma unroll
    for (int i = 0; i < 4; i++) {
        float v = dpv[i];
        v += __shfl_xor_sync(0xffffffffu, v, 1);
        v += __shfl_xor_sync(0xffffffffu, v, 2);
        dpv[i] = v;
    }
    if ((lane & 3) == 0) {
        #pragma unroll
        for (int mt = 0; mt < 2; mt++)
            #pragma unroll
            for (int rh = 0; rh < 2; rh++) {
                int row = q0 + mt * 16 + rh * 8 + (lane >> 2);
                dsum[row * 4 + kw] = dpv[mt * 2 + rh];
            }
    }
    __syncthreads();
    if (tid < 64)
        dinv[tid] = 1.0f / (dsum[tid * 4] + dsum[tid * 4 + 1] +
                            dsum[tid * 4 + 2] + dsum[tid * 4 + 3]);
    __syncthreads();

    // ---- epilogue: out = gamma * o / denom + x ----
    const float gv = gamma[0];
    #pragma unroll
    for (int mt = 0; mt < 2; mt++) {
        int r0 = q0 + mt * 16 + (lane >> 2);
        float s0 = gv * dinv[r0];
        float s1 = gv * dinv[r0 + 8];
        #pragma unroll
        for (int ct = 0; ct < 8; ct++) {
            size_t g0 = (boff + qbase + r0) * CDIM + chbase + kw * 64 + ct * 8 + (lane & 3) * 2;
            size_t g1 = g0 + (size_t)8 * CDIM;
            float2 xv0 = *(const float2*)(x + g0);
            float2 xv1 = *(const float2*)(x + g1);
            float2 o0, o1;
            o0.x = s0 * acc[mt][ct][0] + xv0.x;
            o0.y = s0 * acc[mt][ct][1] + xv0.y;
            o1.x = s1 * acc[mt][ct][2] + xv1.x;
            o1.y = s1 * acc[mt][ct][3] + xv1.y;
            *(float2*)(out + g0) = o0;
            *(float2*)(out + g1) = o1;
        }
    }
}

// ---------------------------------------------------------------------------
extern "C" void kernel_launch(void* const* d_in, const int* in_sizes, int n_in,
                              void* d_out, int out_size)
{
    const float* x     = (const float*)d_in[0];
    const float* in_h  = (const float*)d_in[1];
    const float* f     = (const float*)d_in[2];
    const float* g     = (const float*)d_in[3];
    const float* gamma = (const float*)d_in[4];
    float* out = (float*)d_out;

    cudaFuncSetAttribute(attn_kernel, cudaFuncAttributeMaxDynamicSharedMemorySize, SMEM_TOTAL);

    proj_kernel<<<dim3((NB * NSEQ) / 128, 1, 2), 256>>>(x, in_h, f, g);
    attn_kernel<<<dim3(NSEQ / 64, 2, NB), 256, SMEM_TOTAL>>>(x, gamma, out);
}